// round 3
// baseline (speedup 1.0000x reference)
#include <cuda_runtime.h>
#include <math.h>

#define BATCH 8
#define CCH   256
#define DD    32
#define NN    4096
#define BM    64
#define BN    64
#define PT_STRIDE 68
#define VS_STRIDE 68

// Scratch for q/k/v projections (allocation-free rule: __device__ globals)
__device__ float g_q[BATCH * DD * NN];     // [b][d][n]
__device__ float g_k[BATCH * DD * NN];     // [b][d][n]
__device__ float g_v[BATCH * CCH * NN];    // [b][c][n]

// ---------------------------------------------------------------------------
// Projection GEMM: out[b][r][n] = sum_c W[r][c] * x[b][c][n] + bias[r]
// Tile: 32 rows x 128 cols, K chunks of 32 over C=256. 256 threads.
// ---------------------------------------------------------------------------
__global__ __launch_bounds__(256) void proj_kernel(
    const float* __restrict__ W, const float* __restrict__ bias,
    const float* __restrict__ x, float* __restrict__ out, int R)
{
    __shared__ float Ws[32 * 33];     // [r][c], pad 1
    __shared__ float Xs[32 * 132];    // [c][n], pad 4 (float4 aligned)

    const int b  = blockIdx.z;
    const int r0 = blockIdx.y * 32;
    const int n0 = blockIdx.x * 128;
    const int tid = threadIdx.x;
    const int ty = tid >> 5;          // 0..7  (warp id; uniform per warp)
    const int tx = tid & 31;

    const float* xb = x + (size_t)b * CCH * NN;
    float* ob = out + (size_t)b * R * NN;

    float acc[4][4];
    #pragma unroll
    for (int r = 0; r < 4; r++) {
        float bv = bias[r0 + ty * 4 + r];
        acc[r][0] = bv; acc[r][1] = bv; acc[r][2] = bv; acc[r][3] = bv;
    }

    for (int c0 = 0; c0 < CCH; c0 += 32) {
        __syncthreads();
        // Ws: 32x32, coalesced along c; shared stride 33 -> conflict-free
        for (int i = tid; i < 32 * 32; i += 256) {
            int r = i >> 5, c = i & 31;
            Ws[r * 33 + c] = W[(size_t)(r0 + r) * CCH + c0 + c];
        }
        // Xs: 32 c-rows x 128 n, float4 loads, coalesced along n
        for (int i = tid; i < 32 * 32; i += 256) {
            int c = i >> 5, nq = i & 31;
            *(float4*)&Xs[c * 132 + nq * 4] =
                *(const float4*)&xb[(size_t)(c0 + c) * NN + n0 + nq * 4];
        }
        __syncthreads();

        #pragma unroll 8
        for (int kk = 0; kk < 32; kk++) {
            float4 xv = *(const float4*)&Xs[kk * 132 + tx * 4];
            #pragma unroll
            for (int r = 0; r < 4; r++) {
                float wv = Ws[(ty * 4 + r) * 33 + kk];   // warp-broadcast
                acc[r][0] += wv * xv.x;
                acc[r][1] += wv * xv.y;
                acc[r][2] += wv * xv.z;
                acc[r][3] += wv * xv.w;
            }
        }
    }

    #pragma unroll
    for (int r = 0; r < 4; r++) {
        float4 o = make_float4(acc[r][0], acc[r][1], acc[r][2], acc[r][3]);
        *(float4*)&ob[(size_t)(r0 + ty * 4 + r) * NN + n0 + tx * 4] = o;
    }
}

// ---------------------------------------------------------------------------
// Flash attention + fused epilogue:
//   out[b][c][n] = gamma * (sum_m softmax_m(q_n . k_m) * v[c][m]) + x[b][c][n]
// Block: BM=64 queries, loop key tiles of BN=64. 256 threads.
// Thread (lane, warp w): queries {lane, lane+32}, channels [32w, 32w+32).
// ---------------------------------------------------------------------------
__global__ __launch_bounds__(256, 2) void attn_kernel(
    const float* __restrict__ x, const float* __restrict__ gammap,
    float* __restrict__ out)
{
    extern __shared__ float sm[];
    float* Qs = sm;                       // [DD][BM]      2048
    float* Ks = Qs + DD * BM;             // [DD][BN]      2048
    float* Pt = Ks + DD * BN;             // [BN][68]      4352  (transposed scores)
    float* Vs = Pt + BN * PT_STRIDE;      // [CCH][68]    17408  (c-major)
    float* row_m   = Vs + CCH * VS_STRIDE;   // [BM]
    float* row_l   = row_m + BM;             // [BM]
    float* alpha_s = row_l + BM;             // [BM]

    const int b  = blockIdx.y;
    const int q0 = blockIdx.x * BM;
    const int tid  = threadIdx.x;
    const int lane = tid & 31;
    const int w    = tid >> 5;

    const float* qb = g_q + (size_t)b * DD * NN;
    const float* kb = g_k + (size_t)b * DD * NN;
    const float* vb = g_v + (size_t)b * CCH * NN;

    // Load Q tile (Qs[d][q]); coalesced global, conflict-free shared
    for (int i = tid; i < DD * BM; i += 256) {
        int d = i >> 6, q = i & 63;
        Qs[d * BM + q] = qb[(size_t)d * NN + q0 + q];
    }
    if (tid < BM) { row_m[tid] = -1e30f; row_l[tid] = 0.0f; }

    float acc[2][32];
    #pragma unroll
    for (int qi = 0; qi < 2; qi++)
        #pragma unroll
        for (int cc = 0; cc < 32; cc++) acc[qi][cc] = 0.0f;
    __syncthreads();

    const int sq = tid & 63;            // score-phase query
    const int j0 = (tid >> 6) * 16;     // score-phase key group (warp-uniform)
    const int cbase = w * 32;

    for (int m0 = 0; m0 < NN; m0 += BN) {
        // --- load K tile Ks[d][j] ---
        for (int i = tid; i < DD * BN; i += 256) {
            int d = i >> 6, j = i & 63;
            Ks[d * BN + j] = kb[(size_t)d * NN + m0 + j];
        }
        // --- load V tile Vs[c][j] via float4 ---
        for (int i = tid; i < CCH * (BN / 4); i += 256) {
            int c = i >> 4, jq = i & 15;
            *(float4*)&Vs[c * VS_STRIDE + jq * 4] =
                *(const float4*)&vb[(size_t)c * NN + m0 + jq * 4];
        }
        __syncthreads();

        // --- scores: S[q][j] = sum_d Q[d][q] * K[d][j], 16 j per thread ---
        float sreg[16];
        #pragma unroll
        for (int jj = 0; jj < 16; jj++) sreg[jj] = 0.0f;
        #pragma unroll 8
        for (int d = 0; d < DD; d++) {
            float qv = Qs[d * BM + sq];
            const float4* kr = (const float4*)&Ks[d * BN + j0];
            float4 k0 = kr[0], k1 = kr[1], k2 = kr[2], k3 = kr[3];
            sreg[0]  += qv * k0.x; sreg[1]  += qv * k0.y;
            sreg[2]  += qv * k0.z; sreg[3]  += qv * k0.w;
            sreg[4]  += qv * k1.x; sreg[5]  += qv * k1.y;
            sreg[6]  += qv * k1.z; sreg[7]  += qv * k1.w;
            sreg[8]  += qv * k2.x; sreg[9]  += qv * k2.y;
            sreg[10] += qv * k2.z; sreg[11] += qv * k2.w;
            sreg[12] += qv * k3.x; sreg[13] += qv * k3.y;
            sreg[14] += qv * k3.z; sreg[15] += qv * k3.w;
        }
        #pragma unroll
        for (int jj = 0; jj < 16; jj++)
            Pt[(j0 + jj) * PT_STRIDE + sq] = sreg[jj];
        __syncthreads();

        // --- online softmax (one thread per query row) ---
        if (tid < BM) {
            const int q = tid;
            float mold = row_m[q];
            float mnew = mold;
            #pragma unroll 8
            for (int j = 0; j < BN; j++)
                mnew = fmaxf(mnew, Pt[j * PT_STRIDE + q]);
            float al = __expf(mold - mnew);
            float l  = row_l[q] * al;
            #pragma unroll 8
            for (int j = 0; j < BN; j++) {
                float p = __expf(Pt[j * PT_STRIDE + q] - mnew);
                Pt[j * PT_STRIDE + q] = p;
                l += p;
            }
            row_m[q] = mnew; row_l[q] = l; alpha_s[q] = al;
        }
        __syncthreads();

        // --- rescale + PV accumulate ---
        float a0 = alpha_s[lane], a1 = alpha_s[lane + 32];
        #pragma unroll
        for (int cc = 0; cc < 32; cc++) { acc[0][cc] *= a0; acc[1][cc] *= a1; }

        #pragma unroll 2
        for (int jq = 0; jq < BN; jq += 4) {
            float p0a = Pt[(jq + 0) * PT_STRIDE + lane];
            float p1a = Pt[(jq + 1) * PT_STRIDE + lane];
            float p2a = Pt[(jq + 2) * PT_STRIDE + lane];
            float p3a = Pt[(jq + 3) * PT_STRIDE + lane];
            float p0b = Pt[(jq + 0) * PT_STRIDE + lane + 32];
            float p1b = Pt[(jq + 1) * PT_STRIDE + lane + 32];
            float p2b = Pt[(jq + 2) * PT_STRIDE + lane + 32];
            float p3b = Pt[(jq + 3) * PT_STRIDE + lane + 32];
            #pragma unroll
            for (int cc = 0; cc < 32; cc++) {
                float4 vv = *(const float4*)&Vs[(cbase + cc) * VS_STRIDE + jq];
                acc[0][cc] += p0a * vv.x + p1a * vv.y + p2a * vv.z + p3a * vv.w;
                acc[1][cc] += p0b * vv.x + p1b * vv.y + p2b * vv.z + p3b * vv.w;
            }
        }
        __syncthreads();
    }

    // --- epilogue: out = gamma * acc / l + x, coalesced along n ---
    const float g = gammap[0];
    const float inva = g / row_l[lane];
    const float invb = g / row_l[lane + 32];
    const float* xb = x + (size_t)b * CCH * NN;
    float* ob = out + (size_t)b * CCH * NN;
    #pragma unroll
    for (int cc = 0; cc < 32; cc++) {
        size_t base = (size_t)(cbase + cc) * NN + q0;
        ob[base + lane]      = acc[0][cc] * inva + xb[base + lane];
        ob[base + lane + 32] = acc[1][cc] * invb + xb[base + lane + 32];
    }
}

// ---------------------------------------------------------------------------
extern "C" void kernel_launch(void* const* d_in, const int* in_sizes, int n_in,
                              void* d_out, int out_size)
{
    const float* x     = (const float*)d_in[0];
    const float* wq    = (const float*)d_in[1];
    const float* bq    = (const float*)d_in[2];
    const float* wk    = (const float*)d_in[3];
    const float* bk    = (const float*)d_in[4];
    const float* wv    = (const float*)d_in[5];
    const float* bv    = (const float*)d_in[6];
    const float* gamma = (const float*)d_in[7];
    float* out = (float*)d_out;

    float *qptr, *kptr, *vptr;
    cudaGetSymbolAddress((void**)&qptr, g_q);
    cudaGetSymbolAddress((void**)&kptr, g_k);
    cudaGetSymbolAddress((void**)&vptr, g_v);

    dim3 gqk(NN / 128, DD / 32, BATCH);
    proj_kernel<<<gqk, 256>>>(wq, bq, x, qptr, DD);
    proj_kernel<<<gqk, 256>>>(wk, bk, x, kptr, DD);
    dim3 gv(NN / 128, CCH / 32, BATCH);
    proj_kernel<<<gv, 256>>>(wv, bv, x, vptr, CCH);

    const size_t smem = (size_t)(DD * BM + DD * BN + BN * PT_STRIDE +
                                 CCH * VS_STRIDE + 3 * BM) * sizeof(float);
    cudaFuncSetAttribute(attn_kernel,
                         cudaFuncAttributeMaxDynamicSharedMemorySize, (int)smem);
    dim3 ga(NN / BM, BATCH);
    attn_kernel<<<ga, 256, smem>>>(x, gamma, out);
}

// round 8
// speedup vs baseline: 2.1855x; 2.1855x over previous
#include <cuda_runtime.h>
#include <stdint.h>
#include <math.h>

#define BATCH 8
#define CCH   256
#define DD    32
#define NN    4096
#define BM    64
#define BN    64
#define NTILES (NN / BN)

// device scratch (allocation-free rule)
__device__ float g_q[BATCH * DD * NN];    // [b][d][n]
__device__ float g_k[BATCH * DD * NN];    // [b][d][n]
__device__ float g_v[BATCH * CCH * NN];   // [b][c][n]
__device__ float g_qn[BATCH * NN];        // ||q_n||^2
__device__ float g_kmax[BATCH];           // max_n ||k_n||^2

__device__ __forceinline__ uint32_t f2tf(float x) {
    uint32_t u; asm("cvt.rna.tf32.f32 %0, %1;" : "=r"(u) : "f"(x)); return u;
}
__device__ __forceinline__ float tfr(float x) { return __uint_as_float(f2tf(x)); }

// portable tensor-core mma (sm_80+): D[16x8] += A[16x8] * B[8x8]
__device__ __forceinline__ void mma8(float* d, const uint32_t* a, const uint32_t* b) {
    asm volatile("mma.sync.aligned.m16n8k8.row.col.f32.tf32.tf32.f32 "
        "{%0,%1,%2,%3}, {%4,%5,%6,%7}, {%8,%9}, {%0,%1,%2,%3};"
        : "+f"(d[0]), "+f"(d[1]), "+f"(d[2]), "+f"(d[3])
        : "r"(a[0]), "r"(a[1]), "r"(a[2]), "r"(a[3]), "r"(b[0]), "r"(b[1]));
}

// ---------------------------------------------------------------------------
__global__ void init_kmax_kernel() {
    if (threadIdx.x < BATCH) g_kmax[threadIdx.x] = 0.0f;
}

// ---------------------------------------------------------------------------
// Projection GEMM: out[b][r][n] = W[r][:].x[b][:][n] + bias
// ---------------------------------------------------------------------------
__global__ __launch_bounds__(256) void proj_kernel(
    const float* __restrict__ W, const float* __restrict__ bias,
    const float* __restrict__ x, float* __restrict__ out, int R)
{
    __shared__ float Ws[32 * 33];
    __shared__ float Xs[32 * 132];

    const int b  = blockIdx.z;
    const int r0 = blockIdx.y * 32;
    const int n0 = blockIdx.x * 128;
    const int tid = threadIdx.x;
    const int ty = tid >> 5, tx = tid & 31;

    const float* xb = x + (size_t)b * CCH * NN;
    float* ob = out + (size_t)b * R * NN;

    float acc[4][4];
    #pragma unroll
    for (int r = 0; r < 4; r++) {
        float bv = bias[r0 + ty * 4 + r];
        acc[r][0] = bv; acc[r][1] = bv; acc[r][2] = bv; acc[r][3] = bv;
    }
    for (int c0 = 0; c0 < CCH; c0 += 32) {
        __syncthreads();
        for (int i = tid; i < 32 * 32; i += 256) {
            int r = i >> 5, c = i & 31;
            Ws[r * 33 + c] = W[(size_t)(r0 + r) * CCH + c0 + c];
        }
        for (int i = tid; i < 32 * 32; i += 256) {
            int c = i >> 5, nq = i & 31;
            *(float4*)&Xs[c * 132 + nq * 4] =
                *(const float4*)&xb[(size_t)(c0 + c) * NN + n0 + nq * 4];
        }
        __syncthreads();
        #pragma unroll 8
        for (int kk = 0; kk < 32; kk++) {
            float4 xv = *(const float4*)&Xs[kk * 132 + tx * 4];
            #pragma unroll
            for (int r = 0; r < 4; r++) {
                float wv = Ws[(ty * 4 + r) * 33 + kk];
                acc[r][0] += wv * xv.x; acc[r][1] += wv * xv.y;
                acc[r][2] += wv * xv.z; acc[r][3] += wv * xv.w;
            }
        }
    }
    #pragma unroll
    for (int r = 0; r < 4; r++) {
        float4 o = make_float4(acc[r][0], acc[r][1], acc[r][2], acc[r][3]);
        *(float4*)&ob[(size_t)(r0 + ty * 4 + r) * NN + n0 + tx * 4] = o;
    }
}

// ---------------------------------------------------------------------------
// Norms: ||q_n||^2 per n, and max_n ||k_n||^2 per batch
// ---------------------------------------------------------------------------
__global__ __launch_bounds__(128) void norms_kernel() {
    const int b = blockIdx.y;
    const int n = blockIdx.x * 128 + threadIdx.x;
    const float* qb = g_q + (size_t)b * DD * NN;
    const float* kb = g_k + (size_t)b * DD * NN;
    float sq = 0.f, sk = 0.f;
    #pragma unroll
    for (int d = 0; d < DD; d++) {
        float qv = qb[(size_t)d * NN + n]; sq += qv * qv;
        float kv = kb[(size_t)d * NN + n]; sk += kv * kv;
    }
    g_qn[(size_t)b * NN + n] = sq;
    #pragma unroll
    for (int o = 16; o; o >>= 1) sk = fmaxf(sk, __shfl_xor_sync(0xffffffffu, sk, o));
    if ((threadIdx.x & 31) == 0)
        atomicMax((unsigned int*)&g_kmax[b], __float_as_uint(sk));
}

// ---------------------------------------------------------------------------
// Flash attention on mma.sync tf32. 256 threads = 8 warps, BM=64 queries/CTA.
// Warp w: S-phase owns m-tile mi=w&3 (16 q) x n-group ngrp=w>>2 (32 keys);
//         PV-phase owns channels [32w, 32w+32) x all 64 queries.
// No online rescale: scores bounded by Mq = ||q||*max||k|| (Cauchy-Schwarz).
// ---------------------------------------------------------------------------
__global__ __launch_bounds__(256) void attn_kernel(
    const float* __restrict__ x, const float* __restrict__ gammap,
    float* __restrict__ out)
{
    extern __shared__ float smf[];
    float* QB = smf;               // [64 q][36]  (tf32 hi)
    float* QS = QB + 2304;         // [64 q][36]  (tf32 lo)
    float* KB = QS + 2304;         // [32 d][68]  (tf32 hi)
    float* KS = KB + 2176;         // [32 d][68]  (tf32 lo)
    float* PT = KS + 2176;         // [64 j][68]  P transposed
    float* VS = PT + 4352;         // [256 c][68]
    float* MQ = VS + 17408;        // [64]
    float* LP = MQ + 64;           // [2][64] lsum partials
    float* INV = LP + 128;         // [64]

    const int b  = blockIdx.y;
    const int q0 = blockIdx.x * BM;
    const int tid = threadIdx.x;
    const int lane = tid & 31;
    const int w = tid >> 5;
    const int g = lane >> 2, tg = lane & 3;

    const float* qp = g_q + (size_t)b * DD * NN;
    const float* kp = g_k + (size_t)b * DD * NN;
    const float* vp = g_v + (size_t)b * CCH * NN;

    // Q tile fill (split tf32 hi/lo)
    #pragma unroll
    for (int i = 0; i < 8; i++) {
        int idx = tid + i * 256;
        int q = idx & 63, d = idx >> 6;
        float v = qp[(size_t)d * NN + q0 + q];
        float hb = tfr(v);
        QB[q * 36 + d] = hb;
        QS[q * 36 + d] = tfr(v - hb);
    }
    if (tid < 64) MQ[tid] = sqrtf(g_qn[(size_t)b * NN + q0 + tid] * g_kmax[b]);
    __syncthreads();

    const int mi = w & 3, ngrp = w >> 2;
    const float Mqa = MQ[mi * 16 + g];
    const float Mqb = MQ[mi * 16 + g + 8];
    float lsa = 0.f, lsb = 0.f;

    float o[2][8][4];
    #pragma unroll
    for (int ct = 0; ct < 2; ct++)
        #pragma unroll
        for (int qt = 0; qt < 8; qt++)
            { o[ct][qt][0]=0.f; o[ct][qt][1]=0.f; o[ct][qt][2]=0.f; o[ct][qt][3]=0.f; }

    const int kd = tid >> 3, kj8 = (tid & 7) * 8;   // K-fill assignment

    for (int t = 0; t < NTILES; t++) {
        const int m0 = t * BN;
        __syncthreads();   // prev PV reads of VS/PT/KB done

        // K tile fill (split hi/lo)
        #pragma unroll
        for (int u = 0; u < 2; u++) {
            float4 v = *(const float4*)&kp[(size_t)kd * NN + m0 + kj8 + u * 4];
            float4 hb, hs;
            hb.x = tfr(v.x); hs.x = tfr(v.x - hb.x);
            hb.y = tfr(v.y); hs.y = tfr(v.y - hb.y);
            hb.z = tfr(v.z); hs.z = tfr(v.z - hb.z);
            hb.w = tfr(v.w); hs.w = tfr(v.w - hb.w);
            *(float4*)&KB[kd * 68 + kj8 + u * 4] = hb;
            *(float4*)&KS[kd * 68 + kj8 + u * 4] = hs;
        }
        // V tile fill (rna tf32)
        #pragma unroll
        for (int i = 0; i < 16; i++) {
            int idx = tid + i * 256;
            int c = idx >> 4, jg = (idx & 15) * 4;
            float4 v = *(const float4*)&vp[(size_t)c * NN + m0 + jg];
            float4 r = make_float4(tfr(v.x), tfr(v.y), tfr(v.z), tfr(v.w));
            *(float4*)&VS[c * 68 + jg] = r;
        }
        __syncthreads();

        // ---- S = Q.K^T, 3xTF32 compensated ----
        float s[4][4];
        #pragma unroll
        for (int i = 0; i < 16; i++) ((float*)s)[i] = 0.f;
        #pragma unroll
        for (int pass = 0; pass < 3; pass++) {
            const float* Ap = (pass == 2) ? QS : QB;
            const float* Bp = (pass == 1) ? KS : KB;
            #pragma unroll
            for (int k = 0; k < 4; k++) {
                const int d0 = k * 8;
                uint32_t a[4];
                a[0] = __float_as_uint(Ap[(mi * 16 + g) * 36 + d0 + tg]);
                a[1] = __float_as_uint(Ap[(mi * 16 + g + 8) * 36 + d0 + tg]);
                a[2] = __float_as_uint(Ap[(mi * 16 + g) * 36 + d0 + tg + 4]);
                a[3] = __float_as_uint(Ap[(mi * 16 + g + 8) * 36 + d0 + tg + 4]);
                #pragma unroll
                for (int nt = 0; nt < 4; nt++) {
                    const int jb = (ngrp * 4 + nt) * 8;
                    uint32_t bb[2];
                    bb[0] = __float_as_uint(Bp[(d0 + tg) * 68 + jb + g]);
                    bb[1] = __float_as_uint(Bp[(d0 + tg + 4) * 68 + jb + g]);
                    mma8(s[nt], a, bb);
                }
            }
        }
        // ---- P = exp(S - Mq) -> PT (transposed), lsum accumulation ----
        #pragma unroll
        for (int nt = 0; nt < 4; nt++) {
            const int jb = (ngrp * 4 + nt) * 8;
            float p0 = tfr(__expf(s[nt][0] - Mqa));
            float p1 = tfr(__expf(s[nt][1] - Mqa));
            float p2 = tfr(__expf(s[nt][2] - Mqb));
            float p3 = tfr(__expf(s[nt][3] - Mqb));
            lsa += p0 + p1; lsb += p2 + p3;
            const int qa = mi * 16 + g;
            PT[(jb + 2 * tg) * 68 + qa]         = p0;
            PT[(jb + 2 * tg + 1) * 68 + qa]     = p1;
            PT[(jb + 2 * tg) * 68 + qa + 8]     = p2;
            PT[(jb + 2 * tg + 1) * 68 + qa + 8] = p3;
        }
        __syncthreads();

        // ---- O^T[c][q] += V[c][j] . P^T[j][q] ----
        #pragma unroll
        for (int k8 = 0; k8 < 8; k8++) {
            const int j0 = k8 * 8;
            uint32_t av[2][4], bp[8][2];
            #pragma unroll
            for (int ct = 0; ct < 2; ct++) {
                const int cb = w * 32 + ct * 16;
                av[ct][0] = __float_as_uint(VS[(cb + g) * 68 + j0 + tg]);
                av[ct][1] = __float_as_uint(VS[(cb + g + 8) * 68 + j0 + tg]);
                av[ct][2] = __float_as_uint(VS[(cb + g) * 68 + j0 + tg + 4]);
                av[ct][3] = __float_as_uint(VS[(cb + g + 8) * 68 + j0 + tg + 4]);
            }
            #pragma unroll
            for (int qt = 0; qt < 8; qt++) {
                bp[qt][0] = __float_as_uint(PT[(j0 + tg) * 68 + qt * 8 + g]);
                bp[qt][1] = __float_as_uint(PT[(j0 + tg + 4) * 68 + qt * 8 + g]);
            }
            #pragma unroll
            for (int ct = 0; ct < 2; ct++)
                #pragma unroll
                for (int qt = 0; qt < 8; qt++)
                    mma8(o[ct][qt], av[ct], bp[qt]);
        }
    }

    // ---- lsum reduce: over tg lanes, then over the 2 n-group warps ----
    lsa += __shfl_xor_sync(0xffffffffu, lsa, 1);
    lsa += __shfl_xor_sync(0xffffffffu, lsa, 2);
    lsb += __shfl_xor_sync(0xffffffffu, lsb, 1);
    lsb += __shfl_xor_sync(0xffffffffu, lsb, 2);
    if (tg == 0) {
        LP[ngrp * 64 + mi * 16 + g]     = lsa;
        LP[ngrp * 64 + mi * 16 + g + 8] = lsb;
    }
    __syncthreads();
    if (tid < 64) INV[tid] = gammap[0] / (LP[tid] + LP[64 + tid]);
    __syncthreads();

    // ---- epilogue: out = gamma*O/l + x ----
    const float* xb = x + (size_t)b * CCH * NN;
    float* ob = out + (size_t)b * CCH * NN;
    #pragma unroll
    for (int ct = 0; ct < 2; ct++) {
        const int cr = w * 32 + ct * 16 + g;
        #pragma unroll
        for (int qt = 0; qt < 8; qt++) {
            const int qc = qt * 8 + 2 * tg;
            const float i0 = INV[qc], i1 = INV[qc + 1];
            size_t g0 = (size_t)cr * NN + q0 + qc;
            float2 x0 = *(const float2*)&xb[g0];
            *(float2*)&ob[g0] = make_float2(o[ct][qt][0] * i0 + x0.x,
                                            o[ct][qt][1] * i1 + x0.y);
            size_t g1 = (size_t)(cr + 8) * NN + q0 + qc;
            float2 x1 = *(const float2*)&xb[g1];
            *(float2*)&ob[g1] = make_float2(o[ct][qt][2] * i0 + x1.x,
                                            o[ct][qt][3] * i1 + x1.y);
        }
    }
}

// ---------------------------------------------------------------------------
extern "C" void kernel_launch(void* const* d_in, const int* in_sizes, int n_in,
                              void* d_out, int out_size)
{
    const float* x     = (const float*)d_in[0];
    const float* wq    = (const float*)d_in[1];
    const float* bq    = (const float*)d_in[2];
    const float* wk    = (const float*)d_in[3];
    const float* bk    = (const float*)d_in[4];
    const float* wv    = (const float*)d_in[5];
    const float* bv    = (const float*)d_in[6];
    const float* gamma = (const float*)d_in[7];
    float* out = (float*)d_out;

    float *qptr, *kptr, *vptr;
    cudaGetSymbolAddress((void**)&qptr, g_q);
    cudaGetSymbolAddress((void**)&kptr, g_k);
    cudaGetSymbolAddress((void**)&vptr, g_v);

    init_kmax_kernel<<<1, 32>>>();

    dim3 gqk(NN / 128, DD / 32, BATCH);
    proj_kernel<<<gqk, 256>>>(wq, bq, x, qptr, DD);
    proj_kernel<<<gqk, 256>>>(wk, bk, x, kptr, DD);
    dim3 gv(NN / 128, CCH / 32, BATCH);
    proj_kernel<<<gv, 256>>>(wv, bv, x, vptr, CCH);

    dim3 gn(NN / 128, BATCH);
    norms_kernel<<<gn, 128>>>();

    const int smem = 30976 * (int)sizeof(float);   // 123,904 B
    cudaFuncSetAttribute(attn_kernel,
                         cudaFuncAttributeMaxDynamicSharedMemorySize, smem);
    dim3 ga(NN / BM, BATCH);
    attn_kernel<<<ga, 256, smem>>>(x, gamma, out);
}

// round 10
// speedup vs baseline: 3.8250x; 1.7502x over previous
#include <cuda_runtime.h>
#include <cuda_bf16.h>
#include <stdint.h>
#include <math.h>

#define BATCH 8
#define CCH   256
#define DD    32
#define NN    4096
#define BM    128
#define BN    64
#define NTILES (NN / BN)

// device scratch (allocation-free rule)
__device__ float    g_q[BATCH * DD * NN];          // [b][d][n] fp32
__device__ float    g_k[BATCH * DD * NN];          // [b][d][n] fp32
__device__ uint32_t g_v[BATCH * CCH * NN / 2];     // [b][c][n] bf16 packed
__device__ float    g_qn[BATCH * NN];              // ||q_n||^2
__device__ float    g_kmax[BATCH];                 // max_n ||k_n||^2

// pack two floats -> bf16x2 (lo = first arg, hi = second)
__device__ __forceinline__ uint32_t pkbf(float lo, float hi) {
    uint32_t d;
    asm("cvt.rn.bf16x2.f32 %0, %1, %2;" : "=r"(d) : "f"(hi), "f"(lo));
    return d;
}
__device__ __forceinline__ void ldsm4(uint32_t* r, uint32_t a) {
    asm volatile("ldmatrix.sync.aligned.m8n8.x4.shared.b16 {%0,%1,%2,%3}, [%4];"
        : "=r"(r[0]), "=r"(r[1]), "=r"(r[2]), "=r"(r[3]) : "r"(a));
}
__device__ __forceinline__ void mma16(float* d, const uint32_t* a, uint32_t b0, uint32_t b1) {
    asm volatile("mma.sync.aligned.m16n8k16.row.col.f32.bf16.bf16.f32 "
        "{%0,%1,%2,%3}, {%4,%5,%6,%7}, {%8,%9}, {%0,%1,%2,%3};"
        : "+f"(d[0]), "+f"(d[1]), "+f"(d[2]), "+f"(d[3])
        : "r"(a[0]), "r"(a[1]), "r"(a[2]), "r"(a[3]), "r"(b0), "r"(b1));
}
__device__ __forceinline__ uint32_t smem_u32(const void* p) {
    uint32_t a;
    asm("{ .reg .u64 t; cvta.to.shared.u64 t, %1; cvt.u32.u64 %0, t; }" : "=r"(a) : "l"(p));
    return a;
}

// smem byte offsets
#define OFF_MQ   0        // 512 B
#define OFF_INV  512      // 512 B
#define OFF_QH   1024     // 128 x 80B
#define OFF_QL   11264
#define OFF_KH   21504    // 64 x 80B
#define OFF_KL   26624
#define OFF_P    31744    // 128 x 144B
#define OFF_V    50176    // 256 x 144B
#define SMEM_ATTN 87040

// ---------------------------------------------------------------------------
__global__ void init_kmax_kernel() {
    if (threadIdx.x < BATCH) g_kmax[threadIdx.x] = 0.0f;
}

// ---------------------------------------------------------------------------
// fp32 projection (Q, K): out[b][r][n] = W x + bias
// ---------------------------------------------------------------------------
__global__ __launch_bounds__(256) void proj_kernel(
    const float* __restrict__ W, const float* __restrict__ bias,
    const float* __restrict__ x, float* __restrict__ out, int R)
{
    __shared__ float Ws[32 * 33];
    __shared__ float Xs[32 * 132];
    const int b  = blockIdx.z;
    const int r0 = blockIdx.y * 32;
    const int n0 = blockIdx.x * 128;
    const int tid = threadIdx.x;
    const int ty = tid >> 5, tx = tid & 31;
    const float* xb = x + (size_t)b * CCH * NN;
    float* ob = out + (size_t)b * R * NN;

    float acc[4][4];
    #pragma unroll
    for (int r = 0; r < 4; r++) {
        float bv = bias[r0 + ty * 4 + r];
        acc[r][0] = bv; acc[r][1] = bv; acc[r][2] = bv; acc[r][3] = bv;
    }
    for (int c0 = 0; c0 < CCH; c0 += 32) {
        __syncthreads();
        for (int i = tid; i < 32 * 32; i += 256) {
            int r = i >> 5, c = i & 31;
            Ws[r * 33 + c] = W[(size_t)(r0 + r) * CCH + c0 + c];
        }
        for (int i = tid; i < 32 * 32; i += 256) {
            int c = i >> 5, nq = i & 31;
            *(float4*)&Xs[c * 132 + nq * 4] =
                *(const float4*)&xb[(size_t)(c0 + c) * NN + n0 + nq * 4];
        }
        __syncthreads();
        #pragma unroll 8
        for (int kk = 0; kk < 32; kk++) {
            float4 xv = *(const float4*)&Xs[kk * 132 + tx * 4];
            #pragma unroll
            for (int r = 0; r < 4; r++) {
                float wv = Ws[(ty * 4 + r) * 33 + kk];
                acc[r][0] += wv * xv.x; acc[r][1] += wv * xv.y;
                acc[r][2] += wv * xv.z; acc[r][3] += wv * xv.w;
            }
        }
    }
    #pragma unroll
    for (int r = 0; r < 4; r++) {
        float4 o = make_float4(acc[r][0], acc[r][1], acc[r][2], acc[r][3]);
        *(float4*)&ob[(size_t)(r0 + ty * 4 + r) * NN + n0 + tx * 4] = o;
    }
}

// ---------------------------------------------------------------------------
// V projection writing bf16: g_v[b][c][n]
// ---------------------------------------------------------------------------
__global__ __launch_bounds__(256) void proj_v_bf16(
    const float* __restrict__ W, const float* __restrict__ bias,
    const float* __restrict__ x, uint32_t* __restrict__ out)
{
    __shared__ float Ws[32 * 33];
    __shared__ float Xs[32 * 132];
    const int b  = blockIdx.z;
    const int r0 = blockIdx.y * 32;
    const int n0 = blockIdx.x * 128;
    const int tid = threadIdx.x;
    const int ty = tid >> 5, tx = tid & 31;
    const float* xb = x + (size_t)b * CCH * NN;
    uint32_t* ob = out + (size_t)b * CCH * NN / 2;

    float acc[4][4];
    #pragma unroll
    for (int r = 0; r < 4; r++) {
        float bv = bias[r0 + ty * 4 + r];
        acc[r][0] = bv; acc[r][1] = bv; acc[r][2] = bv; acc[r][3] = bv;
    }
    for (int c0 = 0; c0 < CCH; c0 += 32) {
        __syncthreads();
        for (int i = tid; i < 32 * 32; i += 256) {
            int r = i >> 5, c = i & 31;
            Ws[r * 33 + c] = W[(size_t)(r0 + r) * CCH + c0 + c];
        }
        for (int i = tid; i < 32 * 32; i += 256) {
            int c = i >> 5, nq = i & 31;
            *(float4*)&Xs[c * 132 + nq * 4] =
                *(const float4*)&xb[(size_t)(c0 + c) * NN + n0 + nq * 4];
        }
        __syncthreads();
        #pragma unroll 8
        for (int kk = 0; kk < 32; kk++) {
            float4 xv = *(const float4*)&Xs[kk * 132 + tx * 4];
            #pragma unroll
            for (int r = 0; r < 4; r++) {
                float wv = Ws[(ty * 4 + r) * 33 + kk];
                acc[r][0] += wv * xv.x; acc[r][1] += wv * xv.y;
                acc[r][2] += wv * xv.z; acc[r][3] += wv * xv.w;
            }
        }
    }
    #pragma unroll
    for (int r = 0; r < 4; r++) {
        uint2 o2;
        o2.x = pkbf(acc[r][0], acc[r][1]);
        o2.y = pkbf(acc[r][2], acc[r][3]);
        *(uint2*)&ob[((size_t)(r0 + ty * 4 + r) * NN + n0 + tx * 4) / 2] = o2;
    }
}

// ---------------------------------------------------------------------------
__global__ __launch_bounds__(128) void norms_kernel() {
    const int b = blockIdx.y;
    const int n = blockIdx.x * 128 + threadIdx.x;
    const float* qb = g_q + (size_t)b * DD * NN;
    const float* kb = g_k + (size_t)b * DD * NN;
    float sq = 0.f, sk = 0.f;
    #pragma unroll
    for (int d = 0; d < DD; d++) {
        float qv = qb[(size_t)d * NN + n]; sq += qv * qv;
        float kv = kb[(size_t)d * NN + n]; sk += kv * kv;
    }
    g_qn[(size_t)b * NN + n] = sq;
    #pragma unroll
    for (int o = 16; o; o >>= 1) sk = fmaxf(sk, __shfl_xor_sync(0xffffffffu, sk, o));
    if ((threadIdx.x & 31) == 0)
        atomicMax((unsigned int*)&g_kmax[b], __float_as_uint(sk));
}

// ---------------------------------------------------------------------------
// Flash attention: bf16 m16n8k16 mma + ldmatrix. 256 thr, BM=128 q/CTA.
// S-phase: warp w owns q rows [16w,16w+16) x all 64 j (3-term split-bf16).
// PV-phase: warp w owns c [32w,32w+32) x all 128 q (single bf16).
// No rescale: Mq = ||q||*max||k|| bound.
// ---------------------------------------------------------------------------
__global__ __launch_bounds__(256, 1) void attn_kernel(
    const float* __restrict__ x, const float* __restrict__ gammap,
    float* __restrict__ out)
{
    extern __shared__ char sm[];
    const uint32_t sb = smem_u32(sm);
    float* MQs  = (float*)(sm + OFF_MQ);
    float* INVs = (float*)(sm + OFF_INV);

    const int b  = blockIdx.y;
    const int q0 = blockIdx.x * BM;
    const int tid = threadIdx.x;
    const int lane = tid & 31;
    const int w = tid >> 5;
    const int g = lane >> 2, tg = lane & 3;
    const int lrow = (lane & 7) + 8 * ((lane >> 3) & 1);
    const int lc16 = (lane >> 4) * 16;

    const float* qp = g_q + (size_t)b * DD * NN;
    const float* kp = g_k + (size_t)b * DD * NN;
    const char*  vpb = (const char*)g_v + (size_t)b * CCH * NN * 2;

    // ---- Q fill: split bf16 hi/lo, rows [q][d] stride 80B ----
    {
        const int q = tid & 127, dh = tid >> 7;       // dh in {0,1}, d0 = 16*dh
        float vq[16], rq[16];
        #pragma unroll
        for (int dd = 0; dd < 16; dd++) {
            float v = qp[(size_t)(16 * dh + dd) * NN + q0 + q];
            float h = __bfloat162float(__float2bfloat16(v));
            vq[dd] = v; rq[dd] = v - h;
        }
        uint4 H0, H1, L0, L1;
        H0.x = pkbf(vq[0], vq[1]);  H0.y = pkbf(vq[2], vq[3]);
        H0.z = pkbf(vq[4], vq[5]);  H0.w = pkbf(vq[6], vq[7]);
        H1.x = pkbf(vq[8], vq[9]);  H1.y = pkbf(vq[10], vq[11]);
        H1.z = pkbf(vq[12], vq[13]); H1.w = pkbf(vq[14], vq[15]);
        L0.x = pkbf(rq[0], rq[1]);  L0.y = pkbf(rq[2], rq[3]);
        L0.z = pkbf(rq[4], rq[5]);  L0.w = pkbf(rq[6], rq[7]);
        L1.x = pkbf(rq[8], rq[9]);  L1.y = pkbf(rq[10], rq[11]);
        L1.z = pkbf(rq[12], rq[13]); L1.w = pkbf(rq[14], rq[15]);
        char* qh_p = sm + OFF_QH + q * 80 + dh * 32;
        char* ql_p = sm + OFF_QL + q * 80 + dh * 32;
        *(uint4*)qh_p = H0; *(uint4*)(qh_p + 16) = H1;
        *(uint4*)ql_p = L0; *(uint4*)(ql_p + 16) = L1;
    }
    if (tid < 128) MQs[tid] = sqrtf(g_qn[(size_t)b * NN + q0 + tid] * g_kmax[b]);
    __syncthreads();

    // cache Q fragments (tile-invariant)
    uint32_t qh[2][4], ql[2][4];
    #pragma unroll
    for (int ks = 0; ks < 2; ks++) {
        ldsm4(qh[ks], sb + OFF_QH + (16 * w + lrow) * 80 + ks * 32 + lc16);
        ldsm4(ql[ks], sb + OFF_QL + (16 * w + lrow) * 80 + ks * 32 + lc16);
    }
    const float Mqa = MQs[16 * w + g];
    const float Mqb = MQs[16 * w + g + 8];
    float lsa = 0.f, lsb = 0.f;

    float o[2][16][4];
    #pragma unroll
    for (int ct = 0; ct < 2; ct++)
        #pragma unroll
        for (int qt = 0; qt < 16; qt++)
            { o[ct][qt][0]=0.f; o[ct][qt][1]=0.f; o[ct][qt][2]=0.f; o[ct][qt][3]=0.f; }

    const int kj_ = tid & 63, kdh = tid >> 6;   // K-fill: row j, d-block of 8

    for (int t = 0; t < NTILES; t++) {
        const int m0 = t * BN;
        __syncthreads();   // prev PV done reading P/V before overwrite

        // ---- K fill: [j][d] stride 80B, split hi/lo ----
        {
            float vk[8], rk[8];
            #pragma unroll
            for (int dd = 0; dd < 8; dd++) {
                float v = kp[(size_t)(8 * kdh + dd) * NN + m0 + kj_];
                float h = __bfloat162float(__float2bfloat16(v));
                vk[dd] = v; rk[dd] = v - h;
            }
            uint4 H, L;
            H.x = pkbf(vk[0], vk[1]); H.y = pkbf(vk[2], vk[3]);
            H.z = pkbf(vk[4], vk[5]); H.w = pkbf(vk[6], vk[7]);
            L.x = pkbf(rk[0], rk[1]); L.y = pkbf(rk[2], rk[3]);
            L.z = pkbf(rk[4], rk[5]); L.w = pkbf(rk[6], rk[7]);
            *(uint4*)(sm + OFF_KH + kj_ * 80 + kdh * 16) = H;
            *(uint4*)(sm + OFF_KL + kj_ * 80 + kdh * 16) = L;
        }
        // ---- V fill: [c][j] stride 144B, bf16 passthrough ----
        {
            const char* vrow = vpb + (size_t)tid * NN * 2 + m0 * 2;
            #pragma unroll
            for (int ch = 0; ch < 8; ch++) {
                uint4 vv = *(const uint4*)(vrow + ch * 16);
                *(uint4*)(sm + OFF_V + tid * 144 + ch * 16) = vv;
            }
        }
        __syncthreads();

        // ---- S = Q.K^T (3-term split bf16) ----
        float s[8][4];
        #pragma unroll
        for (int i = 0; i < 32; i++) ((float*)s)[i] = 0.f;
        #pragma unroll
        for (int ks = 0; ks < 2; ks++) {
            uint32_t kb[4][4];
            #pragma unroll
            for (int i = 0; i < 4; i++)
                ldsm4(kb[i], sb + OFF_KH + (16 * i + lrow) * 80 + ks * 32 + lc16);
            #pragma unroll
            for (int i = 0; i < 4; i++) {
                mma16(s[2 * i],     qh[ks], kb[i][0], kb[i][2]);
                mma16(s[2 * i + 1], qh[ks], kb[i][1], kb[i][3]);
                mma16(s[2 * i],     ql[ks], kb[i][0], kb[i][2]);
                mma16(s[2 * i + 1], ql[ks], kb[i][1], kb[i][3]);
            }
            #pragma unroll
            for (int i = 0; i < 4; i++)
                ldsm4(kb[i], sb + OFF_KL + (16 * i + lrow) * 80 + ks * 32 + lc16);
            #pragma unroll
            for (int i = 0; i < 4; i++) {
                mma16(s[2 * i],     qh[ks], kb[i][0], kb[i][2]);
                mma16(s[2 * i + 1], qh[ks], kb[i][1], kb[i][3]);
            }
        }
        // ---- P = exp(S - Mq) -> bf16 [q][j] rows ----
        {
            char* pr0 = sm + OFF_P + (16 * w + g) * 144 + 4 * tg;
            char* pr1 = sm + OFF_P + (16 * w + g + 8) * 144 + 4 * tg;
            #pragma unroll
            for (int nt = 0; nt < 8; nt++) {
                float p0 = __expf(s[nt][0] - Mqa);
                float p1 = __expf(s[nt][1] - Mqa);
                float p2 = __expf(s[nt][2] - Mqb);
                float p3 = __expf(s[nt][3] - Mqb);
                lsa += p0 + p1; lsb += p2 + p3;
                *(uint32_t*)(pr0 + 16 * nt) = pkbf(p0, p1);
                *(uint32_t*)(pr1 + 16 * nt) = pkbf(p2, p3);
            }
        }
        __syncthreads();

        // ---- O^T[c][q] += V[c][j] . P^T[j][q] ----
        #pragma unroll
        for (int kj = 0; kj < 4; kj++) {
            uint32_t av[2][4], bp[8][4];
            #pragma unroll
            for (int ct = 0; ct < 2; ct++)
                ldsm4(av[ct], sb + OFF_V + (32 * w + 16 * ct + lrow) * 144 + kj * 32 + lc16);
            #pragma unroll
            for (int i = 0; i < 8; i++)
                ldsm4(bp[i], sb + OFF_P + (16 * i + lrow) * 144 + kj * 32 + lc16);
            #pragma unroll
            for (int ct = 0; ct < 2; ct++)
                #pragma unroll
                for (int i = 0; i < 8; i++) {
                    mma16(o[ct][2 * i],     av[ct], bp[i][0], bp[i][2]);
                    mma16(o[ct][2 * i + 1], av[ct], bp[i][1], bp[i][3]);
                }
        }
    }

    // ---- lsum reduce (within quad; one warp owns each q row) ----
    lsa += __shfl_xor_sync(0xffffffffu, lsa, 1);
    lsa += __shfl_xor_sync(0xffffffffu, lsa, 2);
    lsb += __shfl_xor_sync(0xffffffffu, lsb, 1);
    lsb += __shfl_xor_sync(0xffffffffu, lsb, 2);
    if (tg == 0) { INVs[16 * w + g] = lsa; INVs[16 * w + g + 8] = lsb; }
    __syncthreads();
    if (tid < 128) INVs[tid] = gammap[0] / INVs[tid];
    __syncthreads();

    // ---- epilogue: out = gamma*O/l + x ----
    const float* xb = x + (size_t)b * CCH * NN;
    float* ob = out + (size_t)b * CCH * NN;
    #pragma unroll
    for (int ct = 0; ct < 2; ct++) {
        const int cr = 32 * w + 16 * ct + g;
        #pragma unroll
        for (int qt = 0; qt < 16; qt++) {
            const int qc = qt * 8 + 2 * tg;
            const float i0 = INVs[qc], i1 = INVs[qc + 1];
            size_t g0 = (size_t)cr * NN + q0 + qc;
            float2 x0 = *(const float2*)&xb[g0];
            *(float2*)&ob[g0] = make_float2(o[ct][qt][0] * i0 + x0.x,
                                            o[ct][qt][1] * i1 + x0.y);
            size_t g1 = (size_t)(cr + 8) * NN + q0 + qc;
            float2 x1 = *(const float2*)&xb[g1];
            *(float2*)&ob[g1] = make_float2(o[ct][qt][2] * i0 + x1.x,
                                            o[ct][qt][3] * i1 + x1.y);
        }
    }
}

// ---------------------------------------------------------------------------
extern "C" void kernel_launch(void* const* d_in, const int* in_sizes, int n_in,
                              void* d_out, int out_size)
{
    const float* x     = (const float*)d_in[0];
    const float* wq    = (const float*)d_in[1];
    const float* bq    = (const float*)d_in[2];
    const float* wk    = (const float*)d_in[3];
    const float* bk    = (const float*)d_in[4];
    const float* wv    = (const float*)d_in[5];
    const float* bv    = (const float*)d_in[6];
    const float* gamma = (const float*)d_in[7];
    float* out = (float*)d_out;

    float *qptr, *kptr;
    uint32_t* vptr;
    cudaGetSymbolAddress((void**)&qptr, g_q);
    cudaGetSymbolAddress((void**)&kptr, g_k);
    cudaGetSymbolAddress((void**)&vptr, g_v);

    init_kmax_kernel<<<1, 32>>>();

    dim3 gqk(NN / 128, DD / 32, BATCH);
    proj_kernel<<<gqk, 256>>>(wq, bq, x, qptr, DD);
    proj_kernel<<<gqk, 256>>>(wk, bk, x, kptr, DD);
    dim3 gv(NN / 128, CCH / 32, BATCH);
    proj_v_bf16<<<gv, 256>>>(wv, bv, x, vptr);

    dim3 gn(NN / 128, BATCH);
    norms_kernel<<<gn, 128>>>();

    cudaFuncSetAttribute(attn_kernel,
                         cudaFuncAttributeMaxDynamicSharedMemorySize, SMEM_ATTN);
    dim3 ga(NN / BM, BATCH);
    attn_kernel<<<ga, 256, SMEM_ATTN>>>(x, gamma, out);
}